// round 11
// baseline (speedup 1.0000x reference)
#include <cuda_runtime.h>

#define OUT_DIM 4096
#define IN_DIM  8192
#define ALPHA   0.001f
#define EPS     1e-12f

// Hierarchy geometry
#define TROWS   64
#define NTILES  (OUT_DIM / TROWS)     // 64 row tiles
#define CCOLS   128
#define NCHUNK  (IN_DIM / CCOLS)      // 64 column chunks

// Scratch (allocation-free)
__device__ float g_y[OUT_DIM];
__device__ float g_yv[OUT_DIM];
__device__ float g_A [NTILES * IN_DIM];   // per-tile column aggregates (2 MB)
__device__ float g_Aex[NTILES * IN_DIM];  // exclusive prefixes         (2 MB)
__device__ float g_ss = 0.0f;             // sum of squares accumulator
__device__ int   g_cnt = 0;               // gemv completion counter
__device__ int   g_cnt2[NCHUNK] = {};     // partials per-chunk counters

// ---------------------------------------------------------------------------
// K1: GEMV + fused normalize (last-block pattern).
// Forward order, DEFAULT policy: leaves tail of W in L2 for K2's reverse read.
// ---------------------------------------------------------------------------
__global__ void __launch_bounds__(256) gemv_kernel(
    const float* __restrict__ W, const float* __restrict__ x,
    float* __restrict__ y, float* __restrict__ yv, float* __restrict__ out_yn)
{
    const int row = blockIdx.x;
    const int tid = threadIdx.x;
    const float4* Wr = reinterpret_cast<const float4*>(W + (size_t)row * IN_DIM);
    const float4* x4 = reinterpret_cast<const float4*>(x);

    float s = 0.0f;
#pragma unroll
    for (int i = tid; i < IN_DIM / 4; i += 256) {
        float4 w = Wr[i];
        float4 v = x4[i];
        s += w.x * v.x + w.y * v.y + w.z * v.z + w.w * v.w;
    }
#pragma unroll
    for (int o = 16; o > 0; o >>= 1) s += __shfl_down_sync(0xFFFFFFFFu, s, o);

    __shared__ float red[8];
    if ((tid & 31) == 0) red[tid >> 5] = s;
    __syncthreads();

    __shared__ int s_last;
    if (tid < 8) {
        s = red[tid];
#pragma unroll
        for (int o = 4; o > 0; o >>= 1) s += __shfl_down_sync(0xFFu, s, o);
        if (tid == 0) {
            y[row] = s;
            atomicAdd(&g_ss, s * s);
            __threadfence();
            const int r = atomicAdd(&g_cnt, 1);
            s_last = (r == OUT_DIM - 1) ? 1 : 0;
        }
    }
    __syncthreads();

    // Last block: normalize epilogue
    if (s_last) {
        __threadfence();   // acquire: see all y[] and g_ss contributions
        __shared__ float s_inv;
        if (tid == 0) {
            const float ss = *((volatile float*)&g_ss);
            s_inv = 1.0f / fmaxf(sqrtf(ss), EPS);
            g_ss  = 0.0f;  // reset for next graph replay
            g_cnt = 0;
        }
        __syncthreads();
        const float inv = s_inv;
#pragma unroll
        for (int i = tid; i < OUT_DIM; i += 256) {
            const float v = y[i] * inv;
            yv[i]     = v;
            out_yn[i] = v;
        }
    }
}

// ---------------------------------------------------------------------------
// K2: per-tile column aggregates + fused tile-scan (per-chunk last block).
// REVERSE tile order: consumes L2-resident tail left by K1, leaves W head
// resident for K3's forward read.
// ---------------------------------------------------------------------------
__global__ void __launch_bounds__(256) partials_kernel(
    const float* __restrict__ W, const float* __restrict__ yv)
{
    __shared__ float4 s_part[8][CCOLS / 4];   // 4 KB
    __shared__ float  s_tot[8][32];
    __shared__ int    s_last;

    const int tid  = threadIdx.x;
    const int l    = tid & 31;                // lane -> float4 column group
    const int w    = tid >> 5;                // warp -> 8-row segment
    const int cc   = blockIdx.x;
    const int t    = (NTILES - 1) - blockIdx.y;   // REVERSE tile order
    const int row0 = t * TROWS;
    const int col0 = cc * CCOLS;

    float4 P = make_float4(0.f, 0.f, 0.f, 0.f);
    {
        const float4* Wp = reinterpret_cast<const float4*>(
            W + (size_t)(row0 + w * 8) * IN_DIM + col0) + l;
        const float* yvp = yv + row0 + w * 8;
#pragma unroll
        for (int j = 0; j < 8; ++j) {
            const float4 wv = Wp[(size_t)j * (IN_DIM / 4)];
            const float  yj = __ldg(yvp + j);
            P.x += wv.x * yj; P.y += wv.y * yj;
            P.z += wv.z * yj; P.w += wv.w * yj;
        }
    }
    s_part[w][l] = P;
    __syncthreads();

    if (w == 0) {
        float4 agg = make_float4(0.f, 0.f, 0.f, 0.f);
#pragma unroll
        for (int ww = 0; ww < 8; ++ww) {
            const float4 p = s_part[ww][l];
            agg.x += p.x; agg.y += p.y; agg.z += p.z; agg.w += p.w;
        }
        reinterpret_cast<float4*>(g_A + (size_t)t * IN_DIM + col0)[l] = agg;
    }
    __syncthreads();   // agg store issued before fence below

    if (tid == 0) {
        __threadfence();
        const int r = atomicAdd(&g_cnt2[cc], 1);
        s_last = (r == NTILES - 1) ? 1 : 0;
        if (s_last) g_cnt2[cc] = 0;   // reset for next replay (only we see it)
    }
    __syncthreads();

    // Last block of this column chunk: exclusive scan of A over 64 tiles
    // for these 128 columns. 8 warps x 8-tile groups, lane <-> column (x4).
    if (s_last) {
        __threadfence();   // acquire all g_A writes for this chunk
#pragma unroll
        for (int c4 = 0; c4 < 4; ++c4) {
            const int col = col0 + c4 * 32 + l;

            float a[8];
#pragma unroll
            for (int j = 0; j < 8; ++j)
                a[j] = g_A[(size_t)(w * 8 + j) * IN_DIM + col];

            float tot = 0.0f;
#pragma unroll
            for (int j = 0; j < 8; ++j) tot += a[j];
            s_tot[w][l] = tot;
            __syncthreads();

            float excl = 0.0f;
#pragma unroll
            for (int ww = 0; ww < 8; ++ww)
                if (ww < w) excl += s_tot[ww][l];

#pragma unroll
            for (int j = 0; j < 8; ++j) {
                g_Aex[(size_t)(w * 8 + j) * IN_DIM + col] = excl;
                excl += a[j];
            }
            __syncthreads();
        }
    }
}

// ---------------------------------------------------------------------------
// K3: apply. FORWARD tile order (hits W head left resident by K2's reverse
// read). No cross-block waits: exclusive prefix from g_Aex.
// ---------------------------------------------------------------------------
__global__ void __launch_bounds__(256, 4) apply_kernel(
    const float* __restrict__ W, const float* __restrict__ x,
    const float* __restrict__ yv, float* __restrict__ Wout)
{
    __shared__ float4 s_part[8][CCOLS / 4];   // 4 KB

    const int tid  = threadIdx.x;
    const int l    = tid & 31;
    const int w    = tid >> 5;
    const int cc   = blockIdx.x;
    const int t    = blockIdx.y;              // FORWARD tile order
    const int row0 = t * TROWS;
    const int col0 = cc * CCOLS;

    float yj[8];
    {
        const float* yvp = yv + row0 + w * 8;
#pragma unroll
        for (int j = 0; j < 8; ++j) yj[j] = __ldg(yvp + j);
    }

    float4 Wr[8];
    {
        const float4* Wp = reinterpret_cast<const float4*>(
            W + (size_t)(row0 + w * 8) * IN_DIM + col0) + l;
#pragma unroll
        for (int j = 0; j < 8; ++j)
            Wr[j] = Wp[(size_t)j * (IN_DIM / 4)];
    }

    float4 P = make_float4(0.f, 0.f, 0.f, 0.f);
#pragma unroll
    for (int j = 0; j < 8; ++j) {
        P.x += Wr[j].x * yj[j]; P.y += Wr[j].y * yj[j];
        P.z += Wr[j].z * yj[j]; P.w += Wr[j].w * yj[j];
    }
    s_part[w][l] = P;
    __syncthreads();

    float4 run = reinterpret_cast<const float4*>(
        g_Aex + (size_t)t * IN_DIM + col0)[l];
#pragma unroll
    for (int ww = 0; ww < 8; ++ww)
        if (ww < w) {
            const float4 p = s_part[ww][l];
            run.x += p.x; run.y += p.y; run.z += p.z; run.w += p.w;
        }

    const float4 xc = reinterpret_cast<const float4*>(x + col0)[l];
    {
        float4* Op = reinterpret_cast<float4*>(
            Wout + (size_t)(row0 + w * 8) * IN_DIM + col0) + l;
#pragma unroll
        for (int j = 0; j < 8; ++j) {
            run.x += Wr[j].x * yj[j]; run.y += Wr[j].y * yj[j];
            run.z += Wr[j].z * yj[j]; run.w += Wr[j].w * yj[j];
            float4 o;
            const float a = ALPHA * yj[j];
            o.x = Wr[j].x + a * (xc.x - run.x);
            o.y = Wr[j].y + a * (xc.y - run.y);
            o.z = Wr[j].z + a * (xc.z - run.z);
            o.w = Wr[j].w + a * (xc.w - run.w);
            __stcs(Op + (size_t)j * (IN_DIM / 4), o);
        }
    }
}

// ---------------------------------------------------------------------------
extern "C" void kernel_launch(void* const* d_in, const int* in_sizes, int n_in,
                              void* d_out, int out_size)
{
    const float* x = (const float*)d_in[0];  // [1, 8192]
    const float* W = (const float*)d_in[1];  // [4096, 8192]
    float* out = (float*)d_out;              // [4096 y_n] ++ [4096*8192 W_new]

    float* y  = nullptr;
    float* yv = nullptr;
    cudaGetSymbolAddress((void**)&y,  g_y);
    cudaGetSymbolAddress((void**)&yv, g_yv);

    gemv_kernel<<<OUT_DIM, 256>>>(W, x, y, yv, out);

    dim3 grid(NCHUNK, NTILES);
    partials_kernel<<<grid, 256>>>(W, yv);
    apply_kernel<<<grid, 256>>>(W, x, yv, out + OUT_DIM);
}

// round 12
// speedup vs baseline: 1.1151x; 1.1151x over previous
#include <cuda_runtime.h>

#define OUT_DIM 4096
#define IN_DIM  8192
#define ALPHA   0.001f
#define EPS     1e-12f

// Hierarchy geometry
#define TROWS   64
#define NTILES  (OUT_DIM / TROWS)     // 64 row tiles
#define CCOLS   128
#define NCHUNK  (IN_DIM / CCOLS)      // 64 column chunks

// Scratch (allocation-free)
__device__ float g_y[OUT_DIM];
__device__ float g_yv[OUT_DIM];
__device__ float g_A [NTILES * IN_DIM];   // per-tile column aggregates (2 MB)
__device__ float g_Aex[NTILES * IN_DIM];  // exclusive prefixes         (2 MB)
__device__ int   g_cnt2[NCHUNK] = {};     // partials per-chunk counters

// ---------------------------------------------------------------------------
// K1: GEMV  y[r] = dot(W[r,:], x).  Pure streaming (no fused epilogue —
// R11 showed the atomic/fence epilogue costs ~10us). Forward order, DEFAULT
// policy: leaves tail of W resident in L2 for K3's reverse read.
// ---------------------------------------------------------------------------
__global__ void __launch_bounds__(256) gemv_kernel(
    const float* __restrict__ W, const float* __restrict__ x, float* __restrict__ y)
{
    const int row = blockIdx.x;
    const int tid = threadIdx.x;
    const float4* Wr = reinterpret_cast<const float4*>(W + (size_t)row * IN_DIM);
    const float4* x4 = reinterpret_cast<const float4*>(x);

    float s = 0.0f;
#pragma unroll
    for (int i = tid; i < IN_DIM / 4; i += 256) {
        float4 w = Wr[i];
        float4 v = x4[i];
        s += w.x * v.x + w.y * v.y + w.z * v.z + w.w * v.w;
    }
#pragma unroll
    for (int o = 16; o > 0; o >>= 1) s += __shfl_down_sync(0xFFFFFFFFu, s, o);

    __shared__ float red[8];
    if ((tid & 31) == 0) red[tid >> 5] = s;
    __syncthreads();
    if (tid < 8) {
        s = red[tid];
#pragma unroll
        for (int o = 4; o > 0; o >>= 1) s += __shfl_down_sync(0xFFu, s, o);
        if (tid == 0) y[row] = s;
    }
}

// ---------------------------------------------------------------------------
// K2: normalize y -> yv, emit y_n
// ---------------------------------------------------------------------------
__global__ void __launch_bounds__(1024) normalize_kernel(
    const float* __restrict__ y, float* __restrict__ yv, float* __restrict__ out_yn)
{
    const int tid = threadIdx.x;

    float ss = 0.0f;
#pragma unroll
    for (int i = tid; i < OUT_DIM; i += 1024) {
        float v = y[i];
        ss += v * v;
    }
#pragma unroll
    for (int o = 16; o > 0; o >>= 1) ss += __shfl_down_sync(0xFFFFFFFFu, ss, o);

    __shared__ float red[32];
    if ((tid & 31) == 0) red[tid >> 5] = ss;
    __syncthreads();
    __shared__ float s_inv;
    if (tid < 32) {
        float t = red[tid];
#pragma unroll
        for (int o = 16; o > 0; o >>= 1) t += __shfl_down_sync(0xFFFFFFFFu, t, o);
        if (tid == 0) s_inv = 1.0f / fmaxf(sqrtf(t), EPS);
    }
    __syncthreads();
    const float inv = s_inv;
#pragma unroll
    for (int i = tid; i < OUT_DIM; i += 1024) {
        float v = y[i] * inv;
        yv[i]     = v;
        out_yn[i] = v;
    }
}

// ---------------------------------------------------------------------------
// K3: per-tile column aggregates + FUSED tile-scan (per-chunk last block).
// REVERSE tile order: consumes L2-resident tail left by K1, leaves W head
// resident for K4's forward read. Default-policy W reads (lines must
// survive in L2 for K4).
// ---------------------------------------------------------------------------
__global__ void __launch_bounds__(256) partials_kernel(
    const float* __restrict__ W, const float* __restrict__ yv)
{
    __shared__ float4 s_part[8][CCOLS / 4];   // 4 KB
    __shared__ float  s_tot[8][32];
    __shared__ int    s_last;

    const int tid  = threadIdx.x;
    const int l    = tid & 31;                // lane -> float4 column group
    const int w    = tid >> 5;                // warp -> 8-row segment
    const int cc   = blockIdx.x;
    const int t    = (NTILES - 1) - blockIdx.y;   // REVERSE tile order
    const int row0 = t * TROWS;
    const int col0 = cc * CCOLS;

    float4 P = make_float4(0.f, 0.f, 0.f, 0.f);
    {
        const float4* Wp = reinterpret_cast<const float4*>(
            W + (size_t)(row0 + w * 8) * IN_DIM + col0) + l;
        const float* yvp = yv + row0 + w * 8;
#pragma unroll
        for (int j = 0; j < 8; ++j) {
            const float4 wv = Wp[(size_t)j * (IN_DIM / 4)];
            const float  yj = __ldg(yvp + j);
            P.x += wv.x * yj; P.y += wv.y * yj;
            P.z += wv.z * yj; P.w += wv.w * yj;
        }
    }
    s_part[w][l] = P;
    __syncthreads();

    if (w == 0) {
        float4 agg = make_float4(0.f, 0.f, 0.f, 0.f);
#pragma unroll
        for (int ww = 0; ww < 8; ++ww) {
            const float4 p = s_part[ww][l];
            agg.x += p.x; agg.y += p.y; agg.z += p.z; agg.w += p.w;
        }
        reinterpret_cast<float4*>(g_A + (size_t)t * IN_DIM + col0)[l] = agg;
    }
    __syncthreads();

    if (tid == 0) {
        __threadfence();
        const int r = atomicAdd(&g_cnt2[cc], 1);
        s_last = (r == NTILES - 1) ? 1 : 0;
        if (s_last) g_cnt2[cc] = 0;   // reset for next graph replay
    }
    __syncthreads();

    // Last block of this column chunk: exclusive scan of A over 64 tiles
    // for these 128 columns. 8 warps x 8-tile groups, lane <-> column (x4).
    if (s_last) {
        __threadfence();   // acquire all g_A writes for this chunk
#pragma unroll
        for (int c4 = 0; c4 < 4; ++c4) {
            const int col = col0 + c4 * 32 + l;

            float a[8];
#pragma unroll
            for (int j = 0; j < 8; ++j)
                a[j] = g_A[(size_t)(w * 8 + j) * IN_DIM + col];

            float tot = 0.0f;
#pragma unroll
            for (int j = 0; j < 8; ++j) tot += a[j];
            s_tot[w][l] = tot;
            __syncthreads();

            float excl = 0.0f;
#pragma unroll
            for (int ww = 0; ww < 8; ++ww)
                if (ww < w) excl += s_tot[ww][l];

#pragma unroll
            for (int j = 0; j < 8; ++j) {
                g_Aex[(size_t)(w * 8 + j) * IN_DIM + col] = excl;
                excl += a[j];
            }
            __syncthreads();
        }
    }
}

// ---------------------------------------------------------------------------
// K4: apply. FORWARD tile order (hits W head left resident by K3).
// W read with __ldlu (LAST-USE): each line is dead after this read, so the
// evict hint lets Wout's write-allocations reuse those L2 slots instead of
// displacing not-yet-read W.
// ---------------------------------------------------------------------------
__global__ void __launch_bounds__(256, 4) apply_kernel(
    const float* __restrict__ W, const float* __restrict__ x,
    const float* __restrict__ yv, float* __restrict__ Wout)
{
    __shared__ float4 s_part[8][CCOLS / 4];   // 4 KB

    const int tid  = threadIdx.x;
    const int l    = tid & 31;
    const int w    = tid >> 5;
    const int cc   = blockIdx.x;
    const int t    = blockIdx.y;              // FORWARD tile order
    const int row0 = t * TROWS;
    const int col0 = cc * CCOLS;

    float yj[8];
    {
        const float* yvp = yv + row0 + w * 8;
#pragma unroll
        for (int j = 0; j < 8; ++j) yj[j] = __ldg(yvp + j);
    }

    float4 Wr[8];
    {
        const float4* Wp = reinterpret_cast<const float4*>(
            W + (size_t)(row0 + w * 8) * IN_DIM + col0) + l;
#pragma unroll
        for (int j = 0; j < 8; ++j)
            Wr[j] = __ldlu(Wp + (size_t)j * (IN_DIM / 4));
    }

    float4 P = make_float4(0.f, 0.f, 0.f, 0.f);
#pragma unroll
    for (int j = 0; j < 8; ++j) {
        P.x += Wr[j].x * yj[j]; P.y += Wr[j].y * yj[j];
        P.z += Wr[j].z * yj[j]; P.w += Wr[j].w * yj[j];
    }
    s_part[w][l] = P;
    __syncthreads();

    float4 run = reinterpret_cast<const float4*>(
        g_Aex + (size_t)t * IN_DIM + col0)[l];
#pragma unroll
    for (int ww = 0; ww < 8; ++ww)
        if (ww < w) {
            const float4 p = s_part[ww][l];
            run.x += p.x; run.y += p.y; run.z += p.z; run.w += p.w;
        }

    const float4 xc = reinterpret_cast<const float4*>(x + col0)[l];
    {
        float4* Op = reinterpret_cast<float4*>(
            Wout + (size_t)(row0 + w * 8) * IN_DIM + col0) + l;
#pragma unroll
        for (int j = 0; j < 8; ++j) {
            run.x += Wr[j].x * yj[j]; run.y += Wr[j].y * yj[j];
            run.z += Wr[j].z * yj[j]; run.w += Wr[j].w * yj[j];
            float4 o;
            const float a = ALPHA * yj[j];
            o.x = Wr[j].x + a * (xc.x - run.x);
            o.y = Wr[j].y + a * (xc.y - run.y);
            o.z = Wr[j].z + a * (xc.z - run.z);
            o.w = Wr[j].w + a * (xc.w - run.w);
            __stcs(Op + (size_t)j * (IN_DIM / 4), o);
        }
    }
}

// ---------------------------------------------------------------------------
extern "C" void kernel_launch(void* const* d_in, const int* in_sizes, int n_in,
                              void* d_out, int out_size)
{
    const float* x = (const float*)d_in[0];  // [1, 8192]
    const float* W = (const float*)d_in[1];  // [4096, 8192]
    float* out = (float*)d_out;              // [4096 y_n] ++ [4096*8192 W_new]

    float* y  = nullptr;
    float* yv = nullptr;
    cudaGetSymbolAddress((void**)&y,  g_y);
    cudaGetSymbolAddress((void**)&yv, g_yv);

    gemv_kernel<<<OUT_DIM, 256>>>(W, x, y);
    normalize_kernel<<<1, 1024>>>(y, yv, out);

    dim3 grid(NCHUNK, NTILES);
    partials_kernel<<<grid, 256>>>(W, yv);
    apply_kernel<<<grid, 256>>>(W, x, yv, out + OUT_DIM);
}